// round 1
// baseline (speedup 1.0000x reference)
#include <cuda_runtime.h>

#define B_  2
#define LQ  1024
#define LK  2048
#define DM  1024
#define NH  16
#define DH  64

// ---------------- scratch (device globals; no allocation allowed) ----------
__device__ float g_Q[B_*NH*LQ*DH];        // [B,H,Lq,dh]   8 MB
__device__ float g_K[B_*NH*LK*DH];        // [B,H,Lk,dh]  16 MB
__device__ float g_V[B_*NH*LK*DH];        // [B,H,Lk,dh]  16 MB
__device__ float g_Ctx[B_*LQ*DM];         // concat heads  8 MB
__device__ float g_attn_fallback[(size_t)B_*NH*LQ*LK]; // 256 MB (only if attn not in d_out)

// ---------------------------------------------------------------------------
// C = X @ W^T + bias.  X:[M,DM], W:[DM,DM] row-major (torch Linear weight).
// headSplit: write out[((b*NH+h)*L + l)*DH + d] with m=b*L+l, n=h*DH+d.
// 128x128 tile, BK=8, 256 threads, 8x8 microtile.
// ---------------------------------------------------------------------------
__global__ __launch_bounds__(256, 2)
void proj_gemm(const float* __restrict__ X, const float* __restrict__ W,
               const float* __restrict__ bias, float* __restrict__ out,
               int L, int headSplit)
{
    __shared__ float As[8][128];
    __shared__ float Bs[8][128];
    const int tid = threadIdx.x;
    const int m0 = blockIdx.y * 128;
    const int n0 = blockIdx.x * 128;
    const int tx = tid & 15, ty = tid >> 4;

    float acc[8][8];
    #pragma unroll
    for (int i = 0; i < 8; i++)
        #pragma unroll
        for (int j = 0; j < 8; j++) acc[i][j] = 0.f;

    const int lr = tid >> 1;        // 0..127 (tile row)
    const int lc = (tid & 1) * 4;   // 0 or 4 (k offset)
    const float* Xp = X + (size_t)(m0 + lr) * DM + lc;
    const float* Wp = W + (size_t)(n0 + lr) * DM + lc;

    for (int k0 = 0; k0 < DM; k0 += 8) {
        float4 xa = *(const float4*)(Xp + k0);
        float4 wb = *(const float4*)(Wp + k0);
        As[lc+0][lr] = xa.x; As[lc+1][lr] = xa.y; As[lc+2][lr] = xa.z; As[lc+3][lr] = xa.w;
        Bs[lc+0][lr] = wb.x; Bs[lc+1][lr] = wb.y; Bs[lc+2][lr] = wb.z; Bs[lc+3][lr] = wb.w;
        __syncthreads();
        #pragma unroll
        for (int k = 0; k < 8; k++) {
            float4 a0 = *(const float4*)&As[k][ty*8];
            float4 a1 = *(const float4*)&As[k][ty*8+4];
            float4 b0 = *(const float4*)&Bs[k][tx*8];
            float4 b1 = *(const float4*)&Bs[k][tx*8+4];
            float a[8] = {a0.x,a0.y,a0.z,a0.w,a1.x,a1.y,a1.z,a1.w};
            float b[8] = {b0.x,b0.y,b0.z,b0.w,b1.x,b1.y,b1.z,b1.w};
            #pragma unroll
            for (int i = 0; i < 8; i++)
                #pragma unroll
                for (int j = 0; j < 8; j++)
                    acc[i][j] += a[i] * b[j];
        }
        __syncthreads();
    }

    #pragma unroll
    for (int i = 0; i < 8; i++) {
        int m = m0 + ty*8 + i;
        #pragma unroll
        for (int j = 0; j < 8; j++) {
            int n = n0 + tx*8 + j;
            float v = acc[i][j] + bias[n];
            if (headSplit) {
                int b = m / L, l = m - b * L;
                int h = n >> 6, d = n & 63;
                out[(((size_t)b*NH + h)*L + l)*DH + d] = v;
            } else {
                out[(size_t)m*DM + n] = v;
            }
        }
    }
}

// ---------------------------------------------------------------------------
// scores: S[b,h,q,k] = (Q.K)/8 + bias, masked -> -1e9.  64x64 tile over dh=64.
// ---------------------------------------------------------------------------
__global__ __launch_bounds__(256, 2)
void scores_kernel(const int* __restrict__ mask, const float* __restrict__ bias,
                   float* __restrict__ P)
{
    const int bh = blockIdx.z;          // b*NH + h
    const int b  = bh / NH;
    const int q0 = blockIdx.y * 64;
    const int k0 = blockIdx.x * 64;
    __shared__ float Qs[DH][64];        // [d][q]
    __shared__ float Ks[DH][64];        // [d][k]
    const float* Qg = g_Q + ((size_t)bh*LQ + q0) * DH;
    const float* Kg = g_K + ((size_t)bh*LK + k0) * DH;
    const int tid = threadIdx.x;

    #pragma unroll
    for (int it = 0; it < 4; it++) {
        int idx = tid + it * 256;       // float4 index 0..1023
        int row = idx >> 4;             // 0..63
        int cv  = (idx & 15) * 4;       // 0..60
        float4 qv = *(const float4*)(Qg + row*DH + cv);
        Qs[cv+0][row]=qv.x; Qs[cv+1][row]=qv.y; Qs[cv+2][row]=qv.z; Qs[cv+3][row]=qv.w;
        float4 kv = *(const float4*)(Kg + row*DH + cv);
        Ks[cv+0][row]=kv.x; Ks[cv+1][row]=kv.y; Ks[cv+2][row]=kv.z; Ks[cv+3][row]=kv.w;
    }
    __syncthreads();

    const int tx = tid & 15, ty = tid >> 4;
    float acc[4][4];
    #pragma unroll
    for (int i = 0; i < 4; i++)
        #pragma unroll
        for (int j = 0; j < 4; j++) acc[i][j] = 0.f;

    #pragma unroll 8
    for (int d = 0; d < DH; d++) {
        float4 av = *(const float4*)&Qs[d][ty*4];
        float4 bv = *(const float4*)&Ks[d][tx*4];
        float a[4] = {av.x, av.y, av.z, av.w};
        float c[4] = {bv.x, bv.y, bv.z, bv.w};
        #pragma unroll
        for (int i = 0; i < 4; i++)
            #pragma unroll
            for (int j = 0; j < 4; j++)
                acc[i][j] += a[i] * c[j];
    }

    #pragma unroll
    for (int i = 0; i < 4; i++) {
        int q = q0 + ty*4 + i;
        #pragma unroll
        for (int j = 0; j < 4; j++) {
            int k = k0 + tx*4 + j;
            size_t off = ((size_t)bh*LQ + q)*LK + k;
            size_t moff = ((size_t)b*LQ + q)*LK + k;
            float s = (mask[moff] == 0) ? -1e9f
                                        : acc[i][j]*0.125f + bias[off];
            P[off] = s;
        }
    }
}

// ---------------------------------------------------------------------------
// In-place row softmax over Lk=2048. One block / row, 256 threads, 8 elems ea.
// ---------------------------------------------------------------------------
__global__ void softmax_kernel(float* __restrict__ P)
{
    const size_t row = blockIdx.x;
    float* p = P + row * LK;
    const int tid = threadIdx.x;
    const int lane = tid & 31, wid = tid >> 5;

    float4 a = ((const float4*)p)[tid];
    float4 c = ((const float4*)p)[tid + 256];

    float m = fmaxf(fmaxf(fmaxf(a.x,a.y),fmaxf(a.z,a.w)),
                    fmaxf(fmaxf(c.x,c.y),fmaxf(c.z,c.w)));
    #pragma unroll
    for (int o = 16; o > 0; o >>= 1) m = fmaxf(m, __shfl_xor_sync(0xffffffffu, m, o));
    __shared__ float red[8];
    if (lane == 0) red[wid] = m;
    __syncthreads();
    float mm = red[0];
    #pragma unroll
    for (int i = 1; i < 8; i++) mm = fmaxf(mm, red[i]);
    __syncthreads();

    a.x = __expf(a.x - mm); a.y = __expf(a.y - mm);
    a.z = __expf(a.z - mm); a.w = __expf(a.w - mm);
    c.x = __expf(c.x - mm); c.y = __expf(c.y - mm);
    c.z = __expf(c.z - mm); c.w = __expf(c.w - mm);

    float s = a.x + a.y + a.z + a.w + c.x + c.y + c.z + c.w;
    #pragma unroll
    for (int o = 16; o > 0; o >>= 1) s += __shfl_xor_sync(0xffffffffu, s, o);
    if (lane == 0) red[wid] = s;
    __syncthreads();
    float tot = red[0];
    #pragma unroll
    for (int i = 1; i < 8; i++) tot += red[i];
    float inv = __frcp_rn(tot);

    a.x *= inv; a.y *= inv; a.z *= inv; a.w *= inv;
    c.x *= inv; c.y *= inv; c.z *= inv; c.w *= inv;
    ((float4*)p)[tid]       = a;
    ((float4*)p)[tid + 256] = c;
}

// ---------------------------------------------------------------------------
// Ctx[b,q, h*64+d] = sum_k P[b,h,q,k] * V[b,h,k,d]
// ---------------------------------------------------------------------------
__global__ __launch_bounds__(256, 2)
void av_kernel(const float* __restrict__ P, float* __restrict__ Ctx)
{
    const int bh = blockIdx.y;
    const int b  = bh / NH, h = bh - b*NH;
    const int q0 = blockIdx.x * 64;
    __shared__ float Ps[32][64];        // [kk][q]
    __shared__ float Vs[32][64];        // [kk][d]
    const float* Pg = P + ((size_t)bh*LQ + q0) * LK;
    const float* Vg = g_V + (size_t)bh * LK * DH;
    const int tid = threadIdx.x, tx = tid & 15, ty = tid >> 4;

    float acc[4][4];
    #pragma unroll
    for (int i = 0; i < 4; i++)
        #pragma unroll
        for (int j = 0; j < 4; j++) acc[i][j] = 0.f;

    for (int k0 = 0; k0 < LK; k0 += 32) {
        #pragma unroll
        for (int it = 0; it < 2; it++) {
            int idx = tid + it * 256;        // 0..511
            int row = idx >> 3;              // 0..63 (q)
            int cv  = (idx & 7) * 4;         // 0..28 (k)
            float4 pv = *(const float4*)(Pg + (size_t)row*LK + k0 + cv);
            Ps[cv+0][row]=pv.x; Ps[cv+1][row]=pv.y; Ps[cv+2][row]=pv.z; Ps[cv+3][row]=pv.w;
        }
        #pragma unroll
        for (int it = 0; it < 2; it++) {
            int idx = tid + it * 256;
            int row = idx >> 4;              // 0..31 (k)
            int cv  = (idx & 15) * 4;        // 0..60 (d)
            *(float4*)&Vs[row][cv] = *(const float4*)(Vg + (size_t)(k0+row)*DH + cv);
        }
        __syncthreads();
        #pragma unroll
        for (int kk = 0; kk < 32; kk++) {
            float4 av = *(const float4*)&Ps[kk][ty*4];
            float4 bv = *(const float4*)&Vs[kk][tx*4];
            float a[4] = {av.x, av.y, av.z, av.w};
            float c[4] = {bv.x, bv.y, bv.z, bv.w};
            #pragma unroll
            for (int i = 0; i < 4; i++)
                #pragma unroll
                for (int j = 0; j < 4; j++)
                    acc[i][j] += a[i] * c[j];
        }
        __syncthreads();
    }

    #pragma unroll
    for (int i = 0; i < 4; i++) {
        int q = q0 + ty*4 + i;
        #pragma unroll
        for (int j = 0; j < 4; j++) {
            int d = tx*4 + j;
            Ctx[((size_t)b*LQ + q)*DM + h*DH + d] = acc[i][j];
        }
    }
}

// ---------------------------------------------------------------------------
extern "C" void kernel_launch(void* const* d_in, const int* in_sizes, int n_in,
                              void* d_out, int out_size)
{
    const float* query = (const float*)d_in[0];
    const float* key   = (const float*)d_in[1];
    const float* value = (const float*)d_in[2];
    const int*   mask  = (const int*)  d_in[3];
    const float* abias = (const float*)d_in[4];
    const float* Wq = (const float*)d_in[5];  const float* bq = (const float*)d_in[6];
    const float* Wk = (const float*)d_in[7];  const float* bk = (const float*)d_in[8];
    const float* Wv = (const float*)d_in[9];  const float* bv = (const float*)d_in[10];
    const float* Wo = (const float*)d_in[11]; const float* bo = (const float*)d_in[12];

    float* out = (float*)d_out;
    const long long OUT_ELEMS  = (long long)B_*LQ*DM;          // 2,097,152
    const long long ATTN_ELEMS = (long long)B_*NH*LQ*LK;       // 67,108,864

    // attn location: appended after `out` in d_out if the harness holds both
    float* attn;
    if ((long long)out_size >= OUT_ELEMS + ATTN_ELEMS) {
        attn = out + OUT_ELEMS;
    } else {
        void* p = nullptr;
        cudaGetSymbolAddress(&p, g_attn_fallback);
        attn = (float*)p;
    }

    float *gq, *gk, *gv, *gctx;
    { void* p; cudaGetSymbolAddress(&p, g_Q);   gq   = (float*)p; }
    { void* p; cudaGetSymbolAddress(&p, g_K);   gk   = (float*)p; }
    { void* p; cudaGetSymbolAddress(&p, g_V);   gv   = (float*)p; }
    { void* p; cudaGetSymbolAddress(&p, g_Ctx); gctx = (float*)p; }

    // 1) projections into head-split layout
    proj_gemm<<<dim3(DM/128, (B_*LQ)/128), 256>>>(query, Wq, bq, gq, LQ, 1);
    proj_gemm<<<dim3(DM/128, (B_*LK)/128), 256>>>(key,   Wk, bk, gk, LK, 1);
    proj_gemm<<<dim3(DM/128, (B_*LK)/128), 256>>>(value, Wv, bv, gv, LK, 1);

    // 2) scores = QK^T/8 + bias, masked
    scores_kernel<<<dim3(LK/64, LQ/64, B_*NH), 256>>>(mask, abias, attn);

    // 3) softmax rows (in place -> final attn output)
    softmax_kernel<<<B_*NH*LQ, 256>>>(attn);

    // 4) context = attn @ V  (concat-head layout)
    av_kernel<<<dim3(LQ/64, B_*NH), 256>>>(attn, gctx);

    // 5) output projection
    proj_gemm<<<dim3(DM/128, (B_*LQ)/128), 256>>>(gctx, Wo, bo, out, LQ, 0);
}